// round 8
// baseline (speedup 1.0000x reference)
#include <cuda_runtime.h>
#include <math.h>

#define BB 4
#define NN 16384
#define CC 128
#define MM 128
#define NS 512
#define ROW (3 + CC)        // 131 floats per pooled row
#define NBOX (BB * MM)      // 512
#define BLOCK 256
#define NWARP (BLOCK / 32)
#define WORDS (NN / 32)     // 512 mask words per box
#define ASPLIT 16           // box-loop split in kA
#define BOXCHUNK (MM / ASPLIT)   // 8 boxes per kA CTA
#define PCHUNK 1024         // points per kA CTA (4 per thread)
#define PCHUNKS (NN / PCHUNK)    // 16
#define GPARTS 8            // gather CTAs per box
#define GROWS (NS / GPARTS) // 64 rows per gather CTA
#define PARTF (GROWS * ROW) // 8384 floats per part (33536 B)

__device__ unsigned g_mask[NBOX * WORDS];   // inside-mask bitmap [box][word]

// ---------------- Kernel A: mask (point-resident, 4 points/thread) ----------------
__global__ __launch_bounds__(BLOCK)
void kA_mask(const float* __restrict__ points,   // [B,N,3]
             const float* __restrict__ boxes)    // [B,M,7]
{
    const int bs   = blockIdx.x;
    const int sb   = bs & (ASPLIT - 1);
    const int pc   = (bs >> 4) & (PCHUNKS - 1);
    const int b    = bs >> 8;
    const int tid  = threadIdx.x;
    const int w    = tid >> 5;
    const int lane = tid & 31;
    const int box0 = sb * BOXCHUNK;

    __shared__ float4 s_prm[BOXCHUNK * 2];        // {cx,cy,cz,hx},{hy,hz,ch,sh}

    if (tid < BOXCHUNK) {
        const float* bx = boxes + (size_t)(b * MM + box0 + tid) * 7;
        const float hx = __fmul_rn(__fadd_rn(bx[3], 2.0f), 0.5f);
        const float hy = __fmul_rn(__fadd_rn(bx[4], 2.0f), 0.5f);
        const float hz = __fmul_rn(__fadd_rn(bx[5], 2.0f), 0.5f);
        const double hd = (double)bx[6];
        s_prm[tid * 2 + 0] = make_float4(bx[0], bx[1], bx[2], hx);
        s_prm[tid * 2 + 1] = make_float4(hy, hz, (float)cos(hd), (float)sin(hd));
    }

    float px[4], py[4], pz[4];
    const int i0 = pc * PCHUNK + tid;
    #pragma unroll
    for (int g = 0; g < 4; ++g) {
        const float* p = points + ((size_t)b * NN + i0 + g * BLOCK) * 3;
        px[g] = p[0]; py[g] = p[1]; pz[g] = p[2];
    }
    __syncthreads();

    unsigned* gm = g_mask + (size_t)(b * MM + box0) * WORDS + pc * (PCHUNK / 32) + w;

    #pragma unroll 2
    for (int bi = 0; bi < BOXCHUNK; ++bi) {
        const float4 A  = s_prm[bi * 2 + 0];
        const float4 Bp = s_prm[bi * 2 + 1];
        unsigned ball[4];
        #pragma unroll
        for (int g = 0; g < 4; ++g) {
            const float sx = px[g] - A.x;
            const float sy = py[g] - A.y;
            const float sz = pz[g] - A.z;
            const float lx = __fadd_rn(__fmul_rn(sx, Bp.z), __fmul_rn(sy, Bp.w));
            const float ly = __fadd_rn(__fmul_rn(-sx, Bp.w), __fmul_rn(sy, Bp.z));
            const bool pred = (fabsf(lx) < A.w) & (fabsf(ly) < Bp.x) & (fabsf(sz) < Bp.y);
            ball[g] = __ballot_sync(0xffffffffu, pred);
        }
        if (lane == 0) {
            #pragma unroll
            for (int g = 0; g < 4; ++g)
                gm[(size_t)bi * WORDS + g * 8] = ball[g];
        }
    }
}

// ---------------- Kernel BC: fused scan + smem-staged gather (8 CTAs/box) ----------------
__global__ __launch_bounds__(BLOCK)
void kBC_gather(const float* __restrict__ points,
                const float* __restrict__ feats,
                float* __restrict__ out)
{
    const int part = blockIdx.x & (GPARTS - 1);
    const int bm   = blockIdx.x >> 3;
    const int b    = bm >> 7;
    const int k0   = part * GROWS;
    const int tid  = threadIdx.x;
    const int w    = tid >> 5;
    const int lane = tid & 31;

    __shared__ int   s_idx[NS];
    __shared__ int   s_row[GROWS];
    __shared__ int   s_wtot[NWARP];
    __shared__ int   s_cnt;
    __shared__ __align__(16) float s_buf[PARTF];   // 16B-aligned staging buffer

    // ---- scan: each thread owns mask words 2t, 2t+1 ----
    const unsigned* gm = g_mask + (size_t)bm * WORDS;
    const unsigned w0 = gm[tid * 2 + 0];
    const unsigned w1 = gm[tid * 2 + 1];
    const int c0 = __popc(w0);
    const int myc = c0 + __popc(w1);

    int scan = myc;
    #pragma unroll
    for (int d = 1; d < 32; d <<= 1) {
        const int v = __shfl_up_sync(0xffffffffu, scan, d);
        if (lane >= d) scan += v;
    }
    if (lane == 31) s_wtot[w] = scan;
    __syncthreads();
    int wbase = 0, tot = 0;
    #pragma unroll
    for (int j = 0; j < NWARP; ++j) {
        const int c = s_wtot[j];
        if (j < w) wbase += c;
        tot += c;
    }
    const int excl = wbase + scan - myc;

    if (excl < NS && myc) {
        int p = excl;
        unsigned ww = w0;
        while (ww) {
            const int bit = __ffs(ww) - 1;
            ww &= ww - 1;
            if (p < NS) s_idx[p] = tid * 64 + bit;
            ++p;
        }
        p = excl + c0;
        ww = w1;
        while (ww) {
            const int bit = __ffs(ww) - 1;
            ww &= ww - 1;
            if (p < NS) s_idx[p] = tid * 64 + 32 + bit;
            ++p;
        }
    }
    if (tid == 0) s_cnt = tot;
    __syncthreads();

    const int cnt = s_cnt;
    const size_t obase = (size_t)bm * NS * ROW + (size_t)k0 * ROW;  // multiple of 4 floats
    const size_t flag_base = (size_t)NBOX * NS * ROW;
    float4* o4 = (float4*)(out + obase);

    if (cnt == 0) {
        for (int e = tid; e < PARTF / 4; e += BLOCK)
            o4[e] = make_float4(0.f, 0.f, 0.f, 0.f);
        if (part == 0 && tid == 0) out[flag_base + bm] = 1.0f;
        return;
    }

    if (tid < GROWS) {
        const int k = k0 + tid;
        s_row[tid] = s_idx[(cnt >= NS) ? k : (k % cnt)];
    }
    if (part == 0 && tid == 0) out[flag_base + bm] = 0.0f;
    __syncthreads();

    const float* pts = points + (size_t)b * NN * 3;
    const float* ft  = feats  + (size_t)b * NN * CC;

    // Phase 1: coalesced gather into smem staging (2 rows/iter/warp)
    #pragma unroll
    for (int i = 0; i < GROWS / (2 * NWARP); ++i) {
        const int r0 = 2 * (w + NWARP * i);
        const int r1 = r0 + 1;
        const int ia = s_row[r0];
        const int ib = s_row[r1];
        const float* sa = ft + (size_t)ia * CC;
        const float* sb = ft + (size_t)ib * CC;

        float av[4], bv[4];
        #pragma unroll
        for (int j = 0; j < 4; ++j) av[j] = sa[lane + 32 * j];
        #pragma unroll
        for (int j = 0; j < 4; ++j) bv[j] = sb[lane + 32 * j];
        float pa = 0.f, pb = 0.f;
        if (lane < 3) { pa = pts[ia * 3 + lane]; pb = pts[ib * 3 + lane]; }

        float* da = s_buf + r0 * ROW;
        float* db = s_buf + r1 * ROW;
        if (lane < 3) { da[lane] = pa; db[lane] = pb; }
        #pragma unroll
        for (int j = 0; j < 4; ++j) da[3 + lane + 32 * j] = av[j];
        #pragma unroll
        for (int j = 0; j < 4; ++j) db[3 + lane + 32 * j] = bv[j];
    }
    __syncthreads();

    // Phase 2: flat aligned float4 copy smem -> gmem (2096 float4)
    const float4* s4 = (const float4*)s_buf;
    #pragma unroll 4
    for (int e = tid; e < PARTF / 4; e += BLOCK)
        o4[e] = s4[e];
}

extern "C" void kernel_launch(void* const* d_in, const int* in_sizes, int n_in,
                              void* d_out, int out_size) {
    const float* points = (const float*)d_in[0];   // [4,16384,3]
    const float* feats  = (const float*)d_in[1];   // [4,16384,128]
    const float* boxes  = (const float*)d_in[2];   // [4,128,7]
    float* out = (float*)d_out;
    kA_mask<<<BB * PCHUNKS * ASPLIT, BLOCK>>>(points, boxes);
    kBC_gather<<<NBOX * GPARTS, BLOCK>>>(points, feats, out);
}